// round 15
// baseline (speedup 1.0000x reference)
#include <cuda_runtime.h>
#include <cstdint>

#define NEG_INF  (-1e8f)
#define M_EMPTY  (-1e30f)
#define INVLN2 1.4426950408889634f
#define LN2    0.6931471805599453f

__device__ __forceinline__ float ex2f(float x){ float r; asm("ex2.approx.ftz.f32 %0, %1;" : "=f"(r) : "f"(x)); return r; }
__device__ __forceinline__ float lg2f(float x){ float r; asm("lg2.approx.ftz.f32 %0, %1;" : "=f"(r) : "f"(x)); return r; }

__device__ __forceinline__ float lse2(float a, float b){
    float m = fmaxf(a, b);
    return m + lg2f(1.0f + ex2f(-fabsf(a - b)));
}
__device__ __forceinline__ float lse3(float a, float b, float c){
    float m = fmaxf(fmaxf(a, b), c);
    return m + lg2f(ex2f(a - m) + ex2f(b - m) + ex2f(c - m));
}
// online-softmax fold, identity (M_EMPTY, 0); branch-free
__device__ __forceinline__ void mqcomb(float& M, float& Q, float Ma, float Qa){
    float f  = ex2f(-fabsf(M - Ma));
    bool  ge = (M >= Ma);
    float q1 = fmaf(Qa, f, Q);
    float q2 = fmaf(Q,  f, Qa);
    Q = ge ? q1 : q2;
    M = fmaxf(M, Ma);
}
__device__ __forceinline__ void st_release_s32(uint32_t saddr, int v){
    asm volatile("st.release.cta.shared::cta.u32 [%0], %1;" :: "r"(saddr), "r"(v) : "memory");
}
__device__ __forceinline__ int ld_acquire_s32(uint32_t saddr){
    int v;
    asm volatile("ld.acquire.cta.shared::cta.u32 %0, [%1];" : "=r"(v) : "r"(saddr) : "memory");
    return v;
}
__device__ __forceinline__ uint32_t smem_u32(const void* p){
    return (uint32_t)__cvta_generic_to_shared(p);
}

// One CTA (4 warps) per TWO batches; warp w = pipeline stage owning cols
// [64w, 64w+64), 2 cols (even/odd) per lane — the proven R12 skeleton.
// Both batches' DPs are statement-interleaved in the same instruction stream:
// two independent dependency chains fill each other's stall gaps (pure ILP,
// no extra warps, no arbiter coupling). Late-fold head pairs; log2 domain;
// S/T factorization; MQ online-softmax scan; smem carry ring per batch.
__global__ __launch_bounds__(128, 1)
void forward_decoder_kernel(const float* __restrict__ theta,
                            const float* __restrict__ A,
                            float* __restrict__ out){
    constexpr int N = 256;
    const int lane = threadIdx.x & 31;
    const int w    = threadIdx.x >> 5;
    const int bA   = blockIdx.x * 2;
    const int bB   = bA + 1;

    __shared__ float4  pay[2][4][8];
    __shared__ uint32_t flag[2][4];
    __shared__ uint32_t ack[2][4];
    if(threadIdx.x < 8){ flag[threadIdx.x >> 2][threadIdx.x & 3] = 0;
                         ack [threadIdx.x >> 2][threadIdx.x & 3] = 0; }
    __syncthreads();   // only CTA barrier

    const int wp = (w + 3) & 3, wn = (w + 1) & 3;
    const uint32_t fprevA = smem_u32(&flag[0][wp]), fownA = smem_u32(&flag[0][w]);
    const uint32_t aownA  = smem_u32(&ack [0][w]),  anxtA = smem_u32(&ack [0][wn]);
    const uint32_t fprevB = smem_u32(&flag[1][wp]), fownB = smem_u32(&flag[1][w]);
    const uint32_t aownB  = smem_u32(&ack [1][w]),  anxtB = smem_u32(&ack [1][wn]);

    const int jc = (w << 6) + (lane << 1);
    const float* thA = theta + (size_t)bA * 196608 + (size_t)jc * 3;
    const float* AbA = A     + (size_t)bA * 589824 + (size_t)jc * 9;
    const float* thB = theta + (size_t)bB * 196608 + (size_t)jc * 3;
    const float* AbB = A     + (size_t)bB * 589824 + (size_t)jc * 9;

    float2 pA[12], pB[12];
    {
        const float2* tpa = (const float2*)thA; const float2* apa = (const float2*)AbA;
        const float2* tpb = (const float2*)thB; const float2* apb = (const float2*)AbB;
        pA[0]=__ldg(tpa); pA[1]=__ldg(tpa+1); pA[2]=__ldg(tpa+2);
        pB[0]=__ldg(tpb); pB[1]=__ldg(tpb+1); pB[2]=__ldg(tpb+2);
        #pragma unroll
        for(int k = 0; k < 9; k++){ pA[3+k]=__ldg(apa+k); pB[3+k]=__ldg(apb+k); }
    }

    // per-batch DP state
    float Apv0e=NEG_INF, Apv1e=NEG_INF, Apv2e=NEG_INF;
    float Apv0o=NEG_INF, Apv1o=NEG_INF, Apv2o=NEG_INF;
    float Au0in=NEG_INF, Au1in=NEG_INF, Axin=NEG_INF;
    float Bpv0e=NEG_INF, Bpv1e=NEG_INF, Bpv2e=NEG_INF;
    float Bpv0o=NEG_INF, Bpv1o=NEG_INF, Bpv2o=NEG_INF;
    float Bu0in=NEG_INF, Bu1in=NEG_INF, Bxin=NEG_INF;

    float bv0 = (w == 0 && lane == 0) ? 0.0f : NEG_INF;
    float APu0e = lse2(fmaf(pA[3].x, INVLN2, bv0),     fmaf(pA[3].y, INVLN2, bv0));
    float APu1e = lse2(fmaf(pA[4].y, INVLN2, NEG_INF), fmaf(pA[5].x, INVLN2, NEG_INF));
    float APn0o = lse2(fmaf(pA[7].y, INVLN2, NEG_INF), fmaf(pA[8].x, INVLN2, NEG_INF));
    float APn1o = lse2(fmaf(pA[9].x, INVLN2, NEG_INF), fmaf(pA[9].y, INVLN2, NEG_INF));
    float BPu0e = lse2(fmaf(pB[3].x, INVLN2, bv0),     fmaf(pB[3].y, INVLN2, bv0));
    float BPu1e = lse2(fmaf(pB[4].y, INVLN2, NEG_INF), fmaf(pB[5].x, INVLN2, NEG_INF));
    float BPn0o = lse2(fmaf(pB[7].y, INVLN2, NEG_INF), fmaf(pB[8].x, INVLN2, NEG_INF));
    float BPn1o = lse2(fmaf(pB[9].x, INVLN2, NEG_INF), fmaf(pB[9].y, INVLN2, NEG_INF));
    float Adlate = bv0, Bdlate = bv0;

    for(int r = 0; r < N; r++){
        // row-r scalars (pair coefs already consumed by previous tail)
        float At2 = pA[1].x*INVLN2, Bt2 = pB[1].x*INVLN2;
        float At2o= pA[2].y*INVLN2, Bt2o= pB[2].y*INVLN2;
        float At0e=pA[0].x, At1e=pA[0].y, At0o=pA[1].y, At1o=pA[2].x;
        float Bt0e=pB[0].x, Bt1e=pB[0].y, Bt0o=pB[1].y, Bt1o=pB[2].x;
        float Ae2=pA[4].x, Ae5=pA[5].y, Ae6=pA[6].x, Ae7=pA[6].y, Ae8=pA[7].x;
        float Ao2=pA[8].y, Ao5=pA[10].x, Ao6=pA[10].y, Ao7=pA[11].x, Ao8=pA[11].y;
        float Be2=pB[4].x, Be5=pB[5].y, Be6=pB[6].x, Be7=pB[6].y, Be8=pB[7].x;
        float Bo2=pB[8].y, Bo5=pB[10].x, Bo6=pB[10].y, Bo7=pB[11].x, Bo8=pB[11].y;

        // prefetch row r+1 for both batches
        if(r + 1 < N){
            const float2* tpa = (const float2*)(thA + (size_t)(r+1)*768);
            const float2* apa = (const float2*)(AbA + (size_t)(r+1)*2304);
            const float2* tpb = (const float2*)(thB + (size_t)(r+1)*768);
            const float2* apb = (const float2*)(AbB + (size_t)(r+1)*2304);
            pA[0]=__ldg(tpa); pA[1]=__ldg(tpa+1); pA[2]=__ldg(tpa+2);
            pB[0]=__ldg(tpb); pB[1]=__ldg(tpb+1); pB[2]=__ldg(tpb+2);
            #pragma unroll
            for(int k = 0; k < 9; k++){ pA[3+k]=__ldg(apa+k); pB[3+k]=__ldg(apb+k); }
        }

        // heads (one late lse2 fold each), interleaved A/B
        float Au0e  = fmaf(At0e, INVLN2, lse2(APu0e, fmaf(Ae2, INVLN2, Adlate)));
        float Bu0e  = fmaf(Bt0e, INVLN2, lse2(BPu0e, fmaf(Be2, INVLN2, Bdlate)));
        float Au1e  = fmaf(At1e, INVLN2, lse2(APu1e, fmaf(Ae5, INVLN2, Apv2e)));
        float Bu1e  = fmaf(Bt1e, INVLN2, lse2(BPu1e, fmaf(Be5, INVLN2, Bpv2e)));
        float Anu0o = fmaf(At0o, INVLN2, lse2(APn0o, fmaf(Ao2, INVLN2, Apv2e)));
        float Bnu0o = fmaf(Bt0o, INVLN2, lse2(BPn0o, fmaf(Bo2, INVLN2, Bpv2e)));
        float Anu1o = fmaf(At1o, INVLN2, lse2(APn1o, fmaf(Ao5, INVLN2, Apv2o)));
        float Bnu1o = fmaf(Bt1o, INVLN2, lse2(BPn1o, fmaf(Bo5, INVLN2, Bpv2o)));

        float Anum0 = __shfl_up_sync(0xffffffffu, Anu0o, 1);
        float Bnum0 = __shfl_up_sync(0xffffffffu, Bnu0o, 1);
        float Anum1 = __shfl_up_sync(0xffffffffu, Anu1o, 1);
        float Bnum1 = __shfl_up_sync(0xffffffffu, Bnu1o, 1);

        // S prefix-sums (both batches, interleaved shfl chains)
        float Aa_e = fmaf(Ae8, INVLN2, At2),  Aa_o = fmaf(Ao8, INVLN2, At2o);
        float Ba_e = fmaf(Be8, INVLN2, Bt2),  Ba_o = fmaf(Bo8, INVLN2, Bt2o);
        float ASin = Aa_e + Aa_o, BSin = Ba_e + Ba_o;
        #pragma unroll
        for(int dlt = 1; dlt < 32; dlt <<= 1){
            float va = __shfl_up_sync(0xffffffffu, ASin, dlt);
            float vb = __shfl_up_sync(0xffffffffu, BSin, dlt);
            ASin += (lane >= dlt) ? va : 0.0f;
            BSin += (lane >= dlt) ? vb : 0.0f;
        }
        float ASl_o = ASin, ASl_e = ASin - Aa_o;
        float BSl_o = BSin, BSl_e = BSin - Ba_o;

        float Ac_o = At2o + lse2(fmaf(Ao6, INVLN2, Au0e),  fmaf(Ao7, INVLN2, Au1e));
        float Bc_o = Bt2o + lse2(fmaf(Bo6, INVLN2, Bu0e),  fmaf(Bo7, INVLN2, Bu1e));
        float Ac_e = At2  + lse2(fmaf(Ae6, INVLN2, Anum0), fmaf(Ae7, INVLN2, Anum1));
        float Bc_e = Bt2  + lse2(fmaf(Be6, INVLN2, Bnum0), fmaf(Be7, INVLN2, Bnum1));
        float ATe  = (lane == 0) ? M_EMPTY : Ac_e - ASl_e;
        float BTe  = (lane == 0) ? M_EMPTY : Bc_e - BSl_e;
        float ATo  = Ac_o - ASl_o;
        float BTo  = Bc_o - BSl_o;

        float AMi = fmaxf(ATe, ATo), AQi = 1.0f + ex2f(-fabsf(ATe - ATo));
        float BMi = fmaxf(BTe, BTo), BQi = 1.0f + ex2f(-fabsf(BTe - BTo));
        #pragma unroll
        for(int dlt = 1; dlt < 32; dlt <<= 1){
            float AMn = __shfl_up_sync(0xffffffffu, AMi, dlt);
            float BMn = __shfl_up_sync(0xffffffffu, BMi, dlt);
            float AQn = __shfl_up_sync(0xffffffffu, AQi, dlt);
            float BQn = __shfl_up_sync(0xffffffffu, BQi, dlt);
            bool take = (lane >= dlt);
            AMn = take ? AMn : M_EMPTY;  AQn = take ? AQn : 0.0f;
            BMn = take ? BMn : M_EMPTY;  BQn = take ? BQn : 0.0f;
            mqcomb(AMi, AQi, AMn, AQn);
            mqcomb(BMi, BQi, BMn, BQn);
        }
        float AeMs = __shfl_up_sync(0xffffffffu, AMi, 1);
        float BeMs = __shfl_up_sync(0xffffffffu, BMi, 1);
        float AeQs = __shfl_up_sync(0xffffffffu, AQi, 1);
        float BeQs = __shfl_up_sync(0xffffffffu, BQi, 1);
        float AWeM = (lane == 0) ? M_EMPTY : AeMs, AWeQ = (lane == 0) ? 0.0f : AeQs;
        float BWeM = (lane == 0) ? M_EMPTY : BeMs, BWeQ = (lane == 0) ? 0.0f : BeQs;
        mqcomb(AWeM, AWeQ, ATe, 1.0f);
        mqcomb(BWeM, BWeQ, BTe, 1.0f);

        // ---- batch A: late carry wait, finish, post ----
        if(w > 0){
            while(ld_acquire_s32(fprevA) < r + 1){ }
            float4 ps = pay[0][w-1][r & 7];
            Au0in = ps.x; Au1in = ps.y; Axin = ps.z;
            if(lane == 0) st_release_s32(aownA, r + 1);
        }
        float Ace0 = At2 + lse2(fmaf(Ae6, INVLN2, Au0in), fmaf(Ae7, INVLN2, Au1in));
        float Acb  = __shfl_sync(0xffffffffu, Ace0 - Aa_e, 0);
        float AzM  = fmaxf(Axin, Acb);
        float AzQ  = 1.0f + ex2f(-fabsf(Axin - Acb));
        mqcomb(AWeM, AWeQ, AzM, AzQ);
        float Ax_e = ASl_e + AWeM + lg2f(AWeQ);
        mqcomb(AMi, AQi, AzM, AzQ);
        float Ax_o = ASl_o + AMi + lg2f(AQi);
        if(w < 3 && lane == 31){
            while(ld_acquire_s32(anxtA) < r - 7){ }
            pay[0][w][r & 7] = make_float4(Anu0o, Anu1o, Ax_o, 0.0f);
            st_release_s32(fownA, r + 1);
        }

        // ---- batch B: late carry wait, finish, post ----
        if(w > 0){
            while(ld_acquire_s32(fprevB) < r + 1){ }
            float4 ps = pay[1][w-1][r & 7];
            Bu0in = ps.x; Bu1in = ps.y; Bxin = ps.z;
            if(lane == 0) st_release_s32(aownB, r + 1);
        }
        float Bce0 = Bt2 + lse2(fmaf(Be6, INVLN2, Bu0in), fmaf(Be7, INVLN2, Bu1in));
        float Bcb  = __shfl_sync(0xffffffffu, Bce0 - Ba_e, 0);
        float BzM  = fmaxf(Bxin, Bcb);
        float BzQ  = 1.0f + ex2f(-fabsf(Bxin - Bcb));
        mqcomb(BWeM, BWeQ, BzM, BzQ);
        float Bx_e = BSl_e + BWeM + lg2f(BWeQ);
        mqcomb(BMi, BQi, BzM, BzQ);
        float Bx_o = BSl_o + BMi + lg2f(BQi);
        if(w < 3 && lane == 31){
            while(ld_acquire_s32(anxtB) < r - 7){ }
            pay[1][w][r & 7] = make_float4(Bnu0o, Bnu1o, Bx_o, 0.0f);
            st_release_s32(fownB, r + 1);
        }

        // ---- tails: head pairs for row r+1 (p* now hold row r+1), off-chain ----
        float Ad0n = (lane == 0) ? Au0in : Anum0;
        float Ad1n = (lane == 0) ? Au1in : Anum1;
        float Bd0n = (lane == 0) ? Bu0in : Bnum0;
        float Bd1n = (lane == 0) ? Bu1in : Bnum1;
        APu0e = lse2(fmaf(pA[3].x, INVLN2, Ad0n),  fmaf(pA[3].y, INVLN2, Ad1n));
        BPu0e = lse2(fmaf(pB[3].x, INVLN2, Bd0n),  fmaf(pB[3].y, INVLN2, Bd1n));
        APu1e = lse2(fmaf(pA[4].y, INVLN2, Au0e),  fmaf(pA[5].x, INVLN2, Au1e));
        BPu1e = lse2(fmaf(pB[4].y, INVLN2, Bu0e),  fmaf(pB[5].x, INVLN2, Bu1e));
        APn0o = lse2(fmaf(pA[7].y, INVLN2, Au0e),  fmaf(pA[8].x, INVLN2, Au1e));
        BPn0o = lse2(fmaf(pB[7].y, INVLN2, Bu0e),  fmaf(pB[8].x, INVLN2, Bu1e));
        APn1o = lse2(fmaf(pA[9].x, INVLN2, Anu0o), fmaf(pA[9].y, INVLN2, Anu1o));
        BPn1o = lse2(fmaf(pB[9].x, INVLN2, Bnu0o), fmaf(pB[9].y, INVLN2, Bnu1o));
        float Asxo = __shfl_up_sync(0xffffffffu, Ax_o, 1);
        float Bsxo = __shfl_up_sync(0xffffffffu, Bx_o, 1);
        Adlate = (lane == 0) ? Axin : Asxo;
        Bdlate = (lane == 0) ? Bxin : Bsxo;

        Apv0e = Au0e;  Apv1e = Au1e;  Apv2e = Ax_e;
        Apv0o = Anu0o; Apv1o = Anu1o; Apv2o = Ax_o;
        Bpv0e = Bu0e;  Bpv1e = Bu1e;  Bpv2e = Bx_e;
        Bpv0o = Bnu0o; Bpv1o = Bnu1o; Bpv2o = Bx_o;
    }

    if(w == 3 && lane == 31){
        out[bA] = LN2 * lse3(Apv0o, Apv1o, Apv2o);
        out[bB] = LN2 * lse3(Bpv0o, Bpv1o, Bpv2o);
    }
}

extern "C" void kernel_launch(void* const* d_in, const int* in_sizes, int n_in,
                              void* d_out, int out_size) {
    const float* theta = (const float*)d_in[0];
    const float* A     = (const float*)d_in[1];
    // d_in[2] = pos: fixed [(-1,-1),(-1,0),(0,-1)] -> (diag, up, left), hard-coded.
    float* out = (float*)d_out;
    int B = out_size;   // 128 batches, 2 per CTA
    forward_decoder_kernel<<<B / 2, 128>>>(theta, A, out);
}

// round 16
// speedup vs baseline: 3.2105x; 3.2105x over previous
#include <cuda_runtime.h>
#include <cstdint>

#define NEG_INF  (-1e8f)
#define M_EMPTY  (-1e30f)
#define INVLN2 1.4426950408889634f
#define LN2    0.6931471805599453f

__device__ __forceinline__ float ex2f(float x){ float r; asm("ex2.approx.ftz.f32 %0, %1;" : "=f"(r) : "f"(x)); return r; }
__device__ __forceinline__ float lg2f(float x){ float r; asm("lg2.approx.ftz.f32 %0, %1;" : "=f"(r) : "f"(x)); return r; }

__device__ __forceinline__ float lse2(float a, float b){
    float m = fmaxf(a, b);
    return m + lg2f(1.0f + ex2f(-fabsf(a - b)));
}
__device__ __forceinline__ float lse3(float a, float b, float c){
    float m = fmaxf(fmaxf(a, b), c);
    return m + lg2f(ex2f(a - m) + ex2f(b - m) + ex2f(c - m));
}
// online-softmax fold, identity (M_EMPTY, 0); branch-free
__device__ __forceinline__ void mqcomb(float& M, float& Q, float Ma, float Qa){
    float f  = ex2f(-fabsf(M - Ma));
    bool  ge = (M >= Ma);
    float q1 = fmaf(Qa, f, Q);
    float q2 = fmaf(Q,  f, Qa);
    Q = ge ? q1 : q2;
    M = fmaxf(M, Ma);
}
__device__ __forceinline__ void st_release_s32(uint32_t saddr, int v){
    asm volatile("st.release.cta.shared::cta.u32 [%0], %1;" :: "r"(saddr), "r"(v) : "memory");
}
__device__ __forceinline__ int ld_acquire_s32(uint32_t saddr){
    int v;
    asm volatile("ld.acquire.cta.shared::cta.u32 %0, [%1];" : "=r"(v) : "r"(saddr) : "memory");
    return v;
}
__device__ __forceinline__ uint32_t smem_u32(const void* p){
    return (uint32_t)__cvta_generic_to_shared(p);
}

// R12 skeleton (4-stage warp pipeline, 191us) + depth-2 prefetch:
// row r+1's coefficients are consumed (tail P-pairs) a FULL iteration after
// their loads issue, so the tail never waits on DRAM long-scoreboard.
// One CTA (4 warps) per batch; warp w owns cols [64w,64w+64), 2 cols/lane.
// Log2-domain DP, S/T factorization, MQ online-softmax scan, late-fold head
// pairs, smem carry ring with acquire/release flags between stage warps.
__global__ __launch_bounds__(128, 1)
void forward_decoder_kernel(const float* __restrict__ theta,
                            const float* __restrict__ A,
                            float* __restrict__ out){
    constexpr int N = 256;
    const int lane = threadIdx.x & 31;
    const int w    = threadIdx.x >> 5;
    const int b    = blockIdx.x;

    __shared__ float4  pay[4][8];
    __shared__ uint32_t flag[4];
    __shared__ uint32_t ack[4];
    if(threadIdx.x < 4){ flag[threadIdx.x] = 0; ack[threadIdx.x] = 0; }
    __syncthreads();   // only barrier in the kernel

    const uint32_t flag_prev = smem_u32(&flag[(w + 3) & 3]);
    const uint32_t flag_own  = smem_u32(&flag[w]);
    const uint32_t ack_own   = smem_u32(&ack[w]);
    const uint32_t ack_next  = smem_u32(&ack[(w + 1) & 3]);

    const int jc = (w << 6) + (lane << 1);
    const float* thb = theta + (size_t)b * 196608 + (size_t)jc * 3;
    const float* Ab  = A     + (size_t)b * 589824 + (size_t)jc * 9;

    auto loadrow = [&](int r, float2* p){
        const float2* tp = (const float2*)(thb + (size_t)r * 768);
        const float2* ap = (const float2*)(Ab  + (size_t)r * 2304);
        p[0]=__ldg(tp); p[1]=__ldg(tp+1); p[2]=__ldg(tp+2);
        #pragma unroll
        for(int k = 0; k < 9; k++) p[3+k] = __ldg(ap + k);
    };

    float2 bufA[12], bufB[12];
    loadrow(0, bufA);            // row 0
    loadrow(1, bufB);            // row 1

    float pv0e=NEG_INF, pv1e=NEG_INF, pv2e=NEG_INF;
    float pv0o=NEG_INF, pv1o=NEG_INF, pv2o=NEG_INF;
    float u0in=NEG_INF, u1in=NEG_INF, xin=NEG_INF;

    // prologue: head-pairs for row 0 from boundary V (NEG_INF; cell(0,0)=0)
    float bv0 = (w == 0 && lane == 0) ? 0.0f : NEG_INF;
    float Pu0e = lse2(fmaf(bufA[3].x, INVLN2, bv0),     fmaf(bufA[3].y, INVLN2, bv0));
    float Pu1e = lse2(fmaf(bufA[4].y, INVLN2, NEG_INF), fmaf(bufA[5].x, INVLN2, NEG_INF));
    float Pn0o = lse2(fmaf(bufA[7].y, INVLN2, NEG_INF), fmaf(bufA[8].x, INVLN2, NEG_INF));
    float Pn1o = lse2(fmaf(bufA[9].x, INVLN2, NEG_INF), fmaf(bufA[9].y, INVLN2, NEG_INF));
    float dlate = bv0;

    // pc = buffer holding row r (overwritten with row r+2 loads this iter);
    // pn = buffer holding row r+1 (loaded a full iteration ago; tail consumes it)
    auto body = [&](int r, float2* pc, float2* pn){
        // extract row-r scalars BEFORE overwriting pc
        float t0e=pc[0].x, t1e=pc[0].y, t2e=pc[1].x*INVLN2;
        float t0o=pc[1].y, t1o=pc[2].x, t2o=pc[2].y*INVLN2;
        float e2=pc[4].x, e5=pc[5].y, e6=pc[6].x, e7=pc[6].y, e8=pc[7].x;
        float o2=pc[8].y, o5=pc[10].x, o6=pc[10].y, o7=pc[11].x, o8=pc[11].y;

        // issue loads for row r+2 into pc (consumed next iter: full-period gap)
        if(r + 2 < N) loadrow(r + 2, pc);

        // heads: single lse2 fold of precomputed pair with the late V2 term
        float u0e  = fmaf(t0e, INVLN2, lse2(Pu0e, fmaf(e2, INVLN2, dlate)));
        float u1e  = fmaf(t1e, INVLN2, lse2(Pu1e, fmaf(e5, INVLN2, pv2e)));
        float nu0o = fmaf(t0o, INVLN2, lse2(Pn0o, fmaf(o2, INVLN2, pv2e)));
        float nu1o = fmaf(t1o, INVLN2, lse2(Pn1o, fmaf(o5, INVLN2, pv2o)));

        float num0 = __shfl_up_sync(0xffffffffu, nu0o, 1);
        float num1 = __shfl_up_sync(0xffffffffu, nu1o, 1);

        // FADD prefix-sum of a (off-chain)
        float a_e = fmaf(e8, INVLN2, t2e), a_o = fmaf(o8, INVLN2, t2o);
        float Sin = a_e + a_o;
        #pragma unroll
        for(int dlt = 1; dlt < 32; dlt <<= 1){
            float v = __shfl_up_sync(0xffffffffu, Sin, dlt);
            Sin += (lane >= dlt) ? v : 0.0f;
        }
        float Sl_o = Sin, Sl_e = Sin - a_o;

        float c_o = t2o + lse2(fmaf(o6, INVLN2, u0e),  fmaf(o7, INVLN2, u1e));
        float c_e = t2e + lse2(fmaf(e6, INVLN2, num0), fmaf(e7, INVLN2, num1));
        float Te  = (lane == 0) ? M_EMPTY : c_e - Sl_e;
        float To  = c_o - Sl_o;

        float Mi = fmaxf(Te, To);
        float Qi = 1.0f + ex2f(-fabsf(Te - To));
        #pragma unroll
        for(int dlt = 1; dlt < 32; dlt <<= 1){
            float Mn = __shfl_up_sync(0xffffffffu, Mi, dlt);
            float Qn = __shfl_up_sync(0xffffffffu, Qi, dlt);
            bool take = (lane >= dlt);
            Mn = take ? Mn : M_EMPTY;
            Qn = take ? Qn : 0.0f;
            mqcomb(Mi, Qi, Mn, Qn);
        }
        float eM = __shfl_up_sync(0xffffffffu, Mi, 1);
        float eQ = __shfl_up_sync(0xffffffffu, Qi, 1);
        float WeM = (lane == 0) ? M_EMPTY : eM;
        float WeQ = (lane == 0) ? 0.0f    : eQ;
        mqcomb(WeM, WeQ, Te, 1.0f);

        // carry from warp w-1 (row r): u0,u1,x at col 64w-1 (late wait)
        if(w > 0){
            while(ld_acquire_s32(flag_prev) < r + 1){ }
            float4 ps = pay[w-1][r & 7];
            u0in = ps.x; u1in = ps.y; xin = ps.z;
            if(lane == 0) st_release_s32(ack_own, r + 1);
        }

        // lane-0 element + incoming x folded post-scan as one (M,Q) element
        float ce0 = t2e + lse2(fmaf(e6, INVLN2, u0in), fmaf(e7, INVLN2, u1in));
        float cb  = __shfl_sync(0xffffffffu, ce0 - a_e, 0);
        float zM  = fmaxf(xin, cb);
        float zQ  = 1.0f + ex2f(-fabsf(xin - cb));

        mqcomb(WeM, WeQ, zM, zQ);
        float x_e = Sl_e + WeM + lg2f(WeQ);
        float XoM = Mi, XoQ = Qi;
        mqcomb(XoM, XoQ, zM, zQ);
        float x_o = Sl_o + XoM + lg2f(XoQ);

        // post carry to warp w+1
        if(w < 3){
            if(lane == 31){
                while(ld_acquire_s32(ack_next) < r - 7){ }
                pay[w][r & 7] = make_float4(nu0o, nu1o, x_o, 0.0f);
                st_release_s32(flag_own, r + 1);
            }
        }

        // TAIL: head-pairs for row r+1 from pn (loaded a full iter ago — no
        // long-scoreboard). Off the x-chain.
        float d0n = (lane == 0) ? u0in : num0;
        float d1n = (lane == 0) ? u1in : num1;
        Pu0e = lse2(fmaf(pn[3].x, INVLN2, d0n),  fmaf(pn[3].y, INVLN2, d1n));
        Pu1e = lse2(fmaf(pn[4].y, INVLN2, u0e),  fmaf(pn[5].x, INVLN2, u1e));
        Pn0o = lse2(fmaf(pn[7].y, INVLN2, u0e),  fmaf(pn[8].x, INVLN2, u1e));
        Pn1o = lse2(fmaf(pn[9].x, INVLN2, nu0o), fmaf(pn[9].y, INVLN2, nu1o));
        float sxo = __shfl_up_sync(0xffffffffu, x_o, 1);
        dlate = (lane == 0) ? xin : sxo;

        pv0e = u0e;  pv1e = u1e;  pv2e = x_e;
        pv0o = nu0o; pv1o = nu1o; pv2o = x_o;
    };

    for(int r = 0; r < N; r += 2){
        body(r,     bufA, bufB);   // consumes row r (bufA), loads r+2 into bufA
        body(r + 1, bufB, bufA);   // consumes row r+1 (bufB), loads r+3 into bufB
    }

    if(w == 3 && lane == 31) out[b] = LN2 * lse3(pv0o, pv1o, pv2o);
}

extern "C" void kernel_launch(void* const* d_in, const int* in_sizes, int n_in,
                              void* d_out, int out_size) {
    const float* theta = (const float*)d_in[0];
    const float* A     = (const float*)d_in[1];
    // d_in[2] = pos: fixed [(-1,-1),(-1,0),(0,-1)] -> (diag, up, left), hard-coded.
    float* out = (float*)d_out;
    int B = out_size;   // 128 batches, one CTA each
    forward_decoder_kernel<<<B, 128>>>(theta, A, out);
}